// round 1
// baseline (speedup 1.0000x reference)
#include <cuda_runtime.h>
#include <cstdint>

// Problem constants (fixed by the dataset problem)
#define BB   2
#define QQ   16384          // 128*128
#define CC   256
#define HH   8
#define PP   4
#define DD   32
#define BEVW 128
#define BEVH 128
#define MTOT (BB*QQ)        // 32768 rows

// ---------------------------------------------------------------------------
// Scratch (no allocation allowed -> __device__ globals)
// ---------------------------------------------------------------------------
__device__ float g_v[MTOT * CC];        // value @ Wv + bv
__device__ float g_mid[MTOT * CC];      // deformable-attn output (pre-Wo)
__device__ float g_off[MTOT * 64];      // sampling offsets (H*P*2)
__device__ float g_logits[MTOT * 32];   // attention logits (H*P)

// ---------------------------------------------------------------------------
// Tiled fp32 GEMM:  C[M,N] = (A (+A2)) @ B + bias (+Res)
// A row-major [M,K], B row-major [K,N]. M,N,K multiples of tiles.
// ---------------------------------------------------------------------------
template <int BM, int BN, int BK, int TM, int TN, bool HAS_A2, bool HAS_RES>
__global__ __launch_bounds__((BM/TM)*(BN/TN))
void sgemm_kernel(const float* __restrict__ A,
                  const float* __restrict__ A2,
                  const float* __restrict__ Bm,
                  const float* __restrict__ bias,
                  const float* __restrict__ Res,
                  float* __restrict__ Cout,
                  int M, int N, int K)
{
    __shared__ float As[BM][BK];
    __shared__ float Bs[BK][BN];

    constexpr int NT = (BM/TM)*(BN/TN);
    const int tx = threadIdx.x;           // 0..BN/TN-1
    const int ty = threadIdx.y;           // 0..BM/TM-1
    const int tid = ty * (BN/TN) + tx;
    const int m0 = blockIdx.y * BM;
    const int n0 = blockIdx.x * BN;

    float acc[TM][TN];
#pragma unroll
    for (int i = 0; i < TM; i++)
#pragma unroll
        for (int j = 0; j < TN; j++) acc[i][j] = 0.f;

    for (int k0 = 0; k0 < K; k0 += BK) {
        // Load A tile: consecutive tid -> consecutive k (coalesced along K)
#pragma unroll
        for (int idx = tid; idx < BM*BK; idx += NT) {
            int m = idx / BK, k = idx % BK;
            size_t ga = (size_t)(m0 + m) * K + k0 + k;
            float a = A[ga];
            if (HAS_A2) a += A2[ga];
            As[m][k] = a;
        }
        // Load B tile: consecutive tid -> consecutive n (coalesced along N)
#pragma unroll
        for (int idx = tid; idx < BK*BN; idx += NT) {
            int k = idx / BN, n = idx % BN;
            Bs[k][n] = Bm[(size_t)(k0 + k) * N + n0 + n];
        }
        __syncthreads();

#pragma unroll
        for (int k = 0; k < BK; k++) {
            float a[TM], b[TN];
#pragma unroll
            for (int i = 0; i < TM; i++) a[i] = As[ty*TM + i][k];
#pragma unroll
            for (int j = 0; j < TN; j++) b[j] = Bs[k][tx*TN + j];
#pragma unroll
            for (int i = 0; i < TM; i++)
#pragma unroll
                for (int j = 0; j < TN; j++)
                    acc[i][j] += a[i] * b[j];
        }
        __syncthreads();
    }

#pragma unroll
    for (int i = 0; i < TM; i++) {
        int m = m0 + ty*TM + i;
#pragma unroll
        for (int j = 0; j < TN; j++) {
            int n = n0 + tx*TN + j;
            float v = acc[i][j] + bias[n];
            if (HAS_RES) v += Res[(size_t)m * N + n];
            Cout[(size_t)m * N + n] = v;
        }
    }
}

// ---------------------------------------------------------------------------
// Deformable sampling: one warp per (bq, head), lane = channel d.
// blockDim = 256 (8 warps = 8 heads), grid = MTOT blocks (one per query row).
// ---------------------------------------------------------------------------
__global__ __launch_bounds__(256)
void deform_sample_kernel(const float* __restrict__ v,       // [B][Q][C]
                          const float* __restrict__ off,     // [MTOT][64]
                          const float* __restrict__ logits,  // [MTOT][32]
                          const float* __restrict__ ref,     // [B][Q][1][2]
                          float* __restrict__ mid)           // [MTOT][C]
{
    const int bq   = blockIdx.x;
    const int h    = threadIdx.x >> 5;
    const int lane = threadIdx.x & 31;
    const int b    = bq >> 14;   // / QQ

    const float rx = ref[(size_t)bq*2 + 0];
    const float ry = ref[(size_t)bq*2 + 1];

    const float* lg = logits + (size_t)bq*32 + h*4;
    float l0 = lg[0], l1 = lg[1], l2 = lg[2], l3 = lg[3];
    float mx = fmaxf(fmaxf(l0, l1), fmaxf(l2, l3));
    float e[4];
    e[0] = expf(l0 - mx); e[1] = expf(l1 - mx);
    e[2] = expf(l2 - mx); e[3] = expf(l3 - mx);
    float inv = 1.f / (e[0] + e[1] + e[2] + e[3]);

    const float* o  = off + (size_t)bq*64 + h*8;
    const float* vb = v + ((size_t)b * QQ) * CC + h*DD + lane;

    float acc = 0.f;
#pragma unroll
    for (int p = 0; p < PP; p++) {
        float aw = e[p] * inv;
        // loc = ref + off/norm ; x = loc_x*W - 0.5 (match reference fp order)
        float x = (rx + o[p*2 + 0] * (1.f/BEVW)) * (float)BEVW - 0.5f;
        float y = (ry + o[p*2 + 1] * (1.f/BEVH)) * (float)BEVH - 0.5f;
        float x0f = floorf(x), y0f = floorf(y);
        float dx = x - x0f,  dy = y - y0f;
        int x0 = (int)x0f, y0 = (int)y0f;

        float w00 = (1.f - dx) * (1.f - dy);
        float w10 = dx * (1.f - dy);
        float w01 = (1.f - dx) * dy;
        float w11 = dx * dy;

        float s = 0.f;
#pragma unroll
        for (int c = 0; c < 4; c++) {
            int ix = x0 + (c & 1);
            int iy = y0 + (c >> 1);
            float w = (c == 0) ? w00 : (c == 1) ? w10 : (c == 2) ? w01 : w11;
            bool valid = (ix >= 0) & (ix < BEVW) & (iy >= 0) & (iy < BEVH);
            int cx = min(max(ix, 0), BEVW - 1);
            int cy = min(max(iy, 0), BEVH - 1);
            float g = vb[(size_t)(cy * BEVW + cx) * CC];
            s += valid ? (g * w) : 0.f;
        }
        acc += aw * s;
    }

    mid[(size_t)bq*CC + h*DD + lane] = acc;
}

// ---------------------------------------------------------------------------
// Launch
// ---------------------------------------------------------------------------
extern "C" void kernel_launch(void* const* d_in, const int* in_sizes, int n_in,
                              void* d_out, int out_size)
{
    const float* query     = (const float*)d_in[0];
    const float* value     = (const float*)d_in[1];
    const float* identity  = (const float*)d_in[2];
    const float* query_pos = (const float*)d_in[3];
    const float* refpts    = (const float*)d_in[4];
    // d_in[5] spatial_shapes, d_in[6] level_start_index: constant for this problem
    const float* Wv   = (const float*)d_in[7];
    const float* bv   = (const float*)d_in[8];
    const float* Woff = (const float*)d_in[9];
    const float* boff = (const float*)d_in[10];
    const float* Ww   = (const float*)d_in[11];
    const float* bw   = (const float*)d_in[12];
    const float* Wo   = (const float*)d_in[13];
    const float* bo   = (const float*)d_in[14];
    float* out = (float*)d_out;

    float *pv, *pmid, *poff, *plog;
    cudaGetSymbolAddress((void**)&pv,   g_v);
    cudaGetSymbolAddress((void**)&pmid, g_mid);
    cudaGetSymbolAddress((void**)&poff, g_off);
    cudaGetSymbolAddress((void**)&plog, g_logits);

    dim3 blk(16, 16);

    // 1) v = value @ Wv + bv                 (32768 x 256 x 256)
    sgemm_kernel<128, 64, 16, 8, 4, false, false>
        <<<dim3(CC/64, MTOT/128), blk>>>(value, nullptr, Wv, bv, nullptr, pv,
                                         MTOT, CC, CC);

    // 2) off = (query+query_pos) @ Woff + boff   (32768 x 64 x 256)
    sgemm_kernel<128, 64, 16, 8, 4, true, false>
        <<<dim3(1, MTOT/128), blk>>>(query, query_pos, Woff, boff, nullptr, poff,
                                     MTOT, 64, CC);

    // 3) logits = (query+query_pos) @ Ww + bw    (32768 x 32 x 256)
    sgemm_kernel<128, 32, 16, 8, 2, true, false>
        <<<dim3(1, MTOT/128), blk>>>(query, query_pos, Ww, bw, nullptr, plog,
                                     MTOT, 32, CC);

    // 4) softmax + bilinear deformable sampling -> mid
    deform_sample_kernel<<<MTOT, 256>>>(pv, poff, plog, refpts, pmid);

    // 5) out = mid @ Wo + bo + identity       (32768 x 256 x 256)
    sgemm_kernel<128, 64, 16, 8, 4, false, true>
        <<<dim3(CC/64, MTOT/128), blk>>>(pmid, nullptr, Wo, bo, identity, out,
                                         MTOT, CC, CC);
}

// round 2
// speedup vs baseline: 3.3367x; 3.3367x over previous
#include <cuda_runtime.h>
#include <cuda_fp16.h>
#include <cstdint>

// Problem constants
#define BB   2
#define QQ   16384
#define CC   256
#define HH   8
#define PP   4
#define DD   32
#define BEVW 128
#define BEVH 128
#define MTOT (BB*QQ)

// Scratch
__device__ float g_v[MTOT * CC];
__device__ float g_mid[MTOT * CC];
__device__ float g_off[MTOT * 64];
__device__ float g_logits[MTOT * 32];

// ---------------------------------------------------------------------------
// PTX helpers
// ---------------------------------------------------------------------------
__device__ __forceinline__ uint32_t smem_u32(const void* p) {
    uint32_t a;
    asm("{ .reg .u64 t; cvta.to.shared.u64 t, %1; cvt.u32.u64 %0, t; }"
        : "=r"(a) : "l"(p));
    return a;
}

__device__ __forceinline__ void ldm_x4(uint32_t& r0, uint32_t& r1, uint32_t& r2,
                                       uint32_t& r3, uint32_t addr) {
    asm volatile("ldmatrix.sync.aligned.m8n8.x4.shared.b16 {%0,%1,%2,%3}, [%4];"
                 : "=r"(r0), "=r"(r1), "=r"(r2), "=r"(r3) : "r"(addr));
}

__device__ __forceinline__ void ldm_x4_trans(uint32_t& r0, uint32_t& r1, uint32_t& r2,
                                             uint32_t& r3, uint32_t addr) {
    asm volatile("ldmatrix.sync.aligned.m8n8.x4.trans.shared.b16 {%0,%1,%2,%3}, [%4];"
                 : "=r"(r0), "=r"(r1), "=r"(r2), "=r"(r3) : "r"(addr));
}

__device__ __forceinline__ void mma16816(float* c, const uint32_t* a,
                                         uint32_t b0, uint32_t b1) {
    asm volatile(
        "mma.sync.aligned.m16n8k16.row.col.f32.f16.f16.f32 "
        "{%0,%1,%2,%3}, {%4,%5,%6,%7}, {%8,%9}, {%0,%1,%2,%3};"
        : "+f"(c[0]), "+f"(c[1]), "+f"(c[2]), "+f"(c[3])
        : "r"(a[0]), "r"(a[1]), "r"(a[2]), "r"(a[3]), "r"(b0), "r"(b1));
}

// ---------------------------------------------------------------------------
// fp16 tensor-core GEMM:  C[M,N] = half(A (+A2)) @ half(B) + bias (+Res)
// A row-major [M,K] fp32, B row-major [K,N] fp32. fp32->fp16 fused into stage.
// BM=128, BK=32, 256 threads = 8 warps (4 x 2), warp tile 32 x (BN/2).
// ---------------------------------------------------------------------------
template <int BN, bool HAS_A2, bool HAS_RES>
__global__ __launch_bounds__(256)
void hgemm_kernel(const float* __restrict__ A,
                  const float* __restrict__ A2,
                  const float* __restrict__ Bm,
                  const float* __restrict__ bias,
                  const float* __restrict__ Res,
                  float* __restrict__ Cout,
                  int M, int N, int K)
{
    constexpr int BM  = 128;
    constexpr int BK  = 32;
    constexpr int PAD = 8;
    constexpr int WTN = BN / 2;      // warp tile N
    constexpr int NF  = WTN / 8;     // n-fragments per warp

    __shared__ __half As[BM][BK + PAD];
    __shared__ __half Bs[BK][BN + PAD];

    const int tid  = threadIdx.x;
    const int warp = tid >> 5;
    const int lane = tid & 31;
    const int wm   = warp & 3;       // 0..3
    const int wn   = warp >> 2;      // 0..1
    const int m0   = blockIdx.y * BM;
    const int n0   = blockIdx.x * BN;

    float acc[2][NF][4];
#pragma unroll
    for (int i = 0; i < 2; i++)
#pragma unroll
        for (int j = 0; j < NF; j++)
#pragma unroll
            for (int k = 0; k < 4; k++) acc[i][j][k] = 0.f;

    for (int k0 = 0; k0 < K; k0 += BK) {
        // ---- Stage A tile (fp32 -> fp16), 128x32 = 1024 float4 loads ----
#pragma unroll
        for (int it = 0; it < 4; it++) {
            int idx = tid + it * 256;
            int r = idx >> 3, c4 = idx & 7;
            const float4 va = *(const float4*)(A + (size_t)(m0 + r) * K + k0 + c4 * 4);
            float x = va.x, y = va.y, z = va.z, w = va.w;
            if (HAS_A2) {
                const float4 vb = *(const float4*)(A2 + (size_t)(m0 + r) * K + k0 + c4 * 4);
                x += vb.x; y += vb.y; z += vb.z; w += vb.w;
            }
            __half2 h0 = __floats2half2_rn(x, y);
            __half2 h1 = __floats2half2_rn(z, w);
            *(__half2*)&As[r][c4 * 4]     = h0;
            *(__half2*)&As[r][c4 * 4 + 2] = h1;
        }
        // ---- Stage B tile (fp32 -> fp16), 32x(BN) ----
#pragma unroll
        for (int it = 0; it < BN / 32; it++) {
            int idx = tid + it * 256;
            int r = idx / (BN / 4), c4 = idx % (BN / 4);
            const float4 v = *(const float4*)(Bm + (size_t)(k0 + r) * N + n0 + c4 * 4);
            __half2 h0 = __floats2half2_rn(v.x, v.y);
            __half2 h1 = __floats2half2_rn(v.z, v.w);
            *(__half2*)&Bs[r][c4 * 4]     = h0;
            *(__half2*)&Bs[r][c4 * 4 + 2] = h1;
        }
        __syncthreads();

        // ---- 2 mma k-steps of 16 ----
#pragma unroll
        for (int ks = 0; ks < 2; ks++) {
            uint32_t a[2][4];
#pragma unroll
            for (int mf = 0; mf < 2; mf++) {
                int row = wm * 32 + mf * 16 + (lane & 15);
                int col = ks * 16 + ((lane >> 4) << 3);
                ldm_x4(a[mf][0], a[mf][1], a[mf][2], a[mf][3],
                       smem_u32(&As[row][col]));
            }
            uint32_t b[NF][2];
#pragma unroll
            for (int nb = 0; nb < NF / 2; nb++) {
                int g    = lane >> 3;
                int krow = ks * 16 + ((g & 1) << 3) + (lane & 7);
                int ncol = wn * WTN + nb * 16 + ((g >> 1) << 3);
                ldm_x4_trans(b[2 * nb][0], b[2 * nb][1],
                             b[2 * nb + 1][0], b[2 * nb + 1][1],
                             smem_u32(&Bs[krow][ncol]));
            }
#pragma unroll
            for (int mf = 0; mf < 2; mf++)
#pragma unroll
                for (int nf = 0; nf < NF; nf++)
                    mma16816(acc[mf][nf], a[mf], b[nf][0], b[nf][1]);
        }
        __syncthreads();
    }

    // ---- Epilogue: bias (+Res), fp32 stores ----
#pragma unroll
    for (int mf = 0; mf < 2; mf++) {
        int r = m0 + wm * 32 + mf * 16 + (lane >> 2);
#pragma unroll
        for (int nf = 0; nf < NF; nf++) {
            int c = n0 + wn * WTN + nf * 8 + ((lane & 3) << 1);
            float b0 = bias[c], b1 = bias[c + 1];
            size_t i0 = (size_t)r * N + c;
            size_t i1 = (size_t)(r + 8) * N + c;
            float2 o0 = make_float2(acc[mf][nf][0] + b0, acc[mf][nf][1] + b1);
            float2 o1 = make_float2(acc[mf][nf][2] + b0, acc[mf][nf][3] + b1);
            if (HAS_RES) {
                float2 q0 = *(const float2*)(Res + i0);
                float2 q1 = *(const float2*)(Res + i1);
                o0.x += q0.x; o0.y += q0.y;
                o1.x += q1.x; o1.y += q1.y;
            }
            *(float2*)(Cout + i0) = o0;
            *(float2*)(Cout + i1) = o1;
        }
    }
}

// ---------------------------------------------------------------------------
// Deformable sampling: one warp per (bq, head), lane = channel d.
// ---------------------------------------------------------------------------
__global__ __launch_bounds__(256)
void deform_sample_kernel(const float* __restrict__ v,
                          const float* __restrict__ off,
                          const float* __restrict__ logits,
                          const float* __restrict__ ref,
                          float* __restrict__ mid)
{
    const int bq   = blockIdx.x;
    const int h    = threadIdx.x >> 5;
    const int lane = threadIdx.x & 31;
    const int b    = bq >> 14;

    const float rx = __ldg(&ref[bq * 2 + 0]) * (float)BEVW - 0.5f;
    const float ry = __ldg(&ref[bq * 2 + 1]) * (float)BEVH - 0.5f;

    const float4 lg = *(const float4*)(logits + bq * 32 + h * 4);
    float mx = fmaxf(fmaxf(lg.x, lg.y), fmaxf(lg.z, lg.w));
    float e0 = __expf(lg.x - mx), e1 = __expf(lg.y - mx);
    float e2 = __expf(lg.z - mx), e3 = __expf(lg.w - mx);
    float inv = 1.f / (e0 + e1 + e2 + e3);
    float aw[4] = {e0 * inv, e1 * inv, e2 * inv, e3 * inv};

    const float4 oA = *(const float4*)(off + (size_t)bq * 64 + h * 8);
    const float4 oB = *(const float4*)(off + (size_t)bq * 64 + h * 8 + 4);
    float ox[4] = {oA.x, oA.z, oB.x, oB.z};
    float oy[4] = {oA.y, oA.w, oB.y, oB.w};

    const float* vb = v + (size_t)b * QQ * CC + h * DD + lane;

    float acc = 0.f;
#pragma unroll
    for (int p = 0; p < PP; p++) {
        // exact reformulation: (ref + off/128)*128 - 0.5 == ref*128 + off - 0.5
        float x = rx + ox[p];
        float y = ry + oy[p];
        float x0f = floorf(x), y0f = floorf(y);
        float dx = x - x0f, dy = y - y0f;
        int x0 = (int)x0f, y0 = (int)y0f;

        float w00 = (1.f - dx) * (1.f - dy);
        float w10 = dx * (1.f - dy);
        float w01 = (1.f - dx) * dy;
        float w11 = dx * dy;

        float s = 0.f;
#pragma unroll
        for (int c = 0; c < 4; c++) {
            int ix = x0 + (c & 1);
            int iy = y0 + (c >> 1);
            float w = (c == 0) ? w00 : (c == 1) ? w10 : (c == 2) ? w01 : w11;
            bool valid = (ix >= 0) & (ix < BEVW) & (iy >= 0) & (iy < BEVH);
            int cx = min(max(ix, 0), BEVW - 1);
            int cy = min(max(iy, 0), BEVH - 1);
            int idx = ((cy << 7) + cx) << 8;     // *CC
            float g = vb[idx];
            s += valid ? (g * w) : 0.f;
        }
        acc = fmaf(aw[p], s, acc);
    }

    mid[(size_t)bq * CC + h * DD + lane] = acc;
}

// ---------------------------------------------------------------------------
// Launch
// ---------------------------------------------------------------------------
extern "C" void kernel_launch(void* const* d_in, const int* in_sizes, int n_in,
                              void* d_out, int out_size)
{
    const float* query     = (const float*)d_in[0];
    const float* value     = (const float*)d_in[1];
    const float* identity  = (const float*)d_in[2];
    const float* query_pos = (const float*)d_in[3];
    const float* refpts    = (const float*)d_in[4];
    const float* Wv   = (const float*)d_in[7];
    const float* bv   = (const float*)d_in[8];
    const float* Woff = (const float*)d_in[9];
    const float* boff = (const float*)d_in[10];
    const float* Ww   = (const float*)d_in[11];
    const float* bw   = (const float*)d_in[12];
    const float* Wo   = (const float*)d_in[13];
    const float* bo   = (const float*)d_in[14];
    float* out = (float*)d_out;

    float *pv, *pmid, *poff, *plog;
    cudaGetSymbolAddress((void**)&pv,   g_v);
    cudaGetSymbolAddress((void**)&pmid, g_mid);
    cudaGetSymbolAddress((void**)&poff, g_off);
    cudaGetSymbolAddress((void**)&plog, g_logits);

    // 1) v = value @ Wv + bv   (32768 x 256 x 256)
    hgemm_kernel<64, false, false>
        <<<dim3(CC / 64, MTOT / 128), 256>>>(value, nullptr, Wv, bv, nullptr, pv,
                                             MTOT, CC, CC);
    // 2) off = (q+qpos) @ Woff + boff   (32768 x 64 x 256)
    hgemm_kernel<64, true, false>
        <<<dim3(1, MTOT / 128), 256>>>(query, query_pos, Woff, boff, nullptr, poff,
                                       MTOT, 64, CC);
    // 3) logits = (q+qpos) @ Ww + bw   (32768 x 32 x 256)
    hgemm_kernel<32, true, false>
        <<<dim3(1, MTOT / 128), 256>>>(query, query_pos, Ww, bw, nullptr, plog,
                                       MTOT, 32, CC);
    // 4) softmax + bilinear sampling
    deform_sample_kernel<<<MTOT, 256>>>(pv, poff, plog, refpts, pmid);
    // 5) out = mid @ Wo + bo + identity   (32768 x 256 x 256)
    hgemm_kernel<64, false, true>
        <<<dim3(CC / 64, MTOT / 128), 256>>>(pmid, nullptr, Wo, bo, identity, out,
                                             MTOT, CC, CC);
}

// round 3
// speedup vs baseline: 5.5280x; 1.6567x over previous
#include <cuda_runtime.h>
#include <cuda_fp16.h>
#include <cstdint>

// Problem constants
#define BB   2
#define QQ   16384
#define CC   256
#define HH   8
#define PP   4
#define DD   32
#define BEVW 128
#define BEVH 128
#define MTOT (BB*QQ)

// Scratch
__device__ float g_v[MTOT * CC];
__device__ float g_mid[MTOT * CC];
__device__ float g_off[MTOT * 64];
__device__ float g_logits[MTOT * 32];

// ---------------------------------------------------------------------------
// PTX helpers
// ---------------------------------------------------------------------------
__device__ __forceinline__ uint32_t smem_u32(const void* p) {
    uint32_t a;
    asm("{ .reg .u64 t; cvta.to.shared.u64 t, %1; cvt.u32.u64 %0, t; }"
        : "=r"(a) : "l"(p));
    return a;
}

__device__ __forceinline__ void ldm_x4(uint32_t& r0, uint32_t& r1, uint32_t& r2,
                                       uint32_t& r3, uint32_t addr) {
    asm volatile("ldmatrix.sync.aligned.m8n8.x4.shared.b16 {%0,%1,%2,%3}, [%4];"
                 : "=r"(r0), "=r"(r1), "=r"(r2), "=r"(r3) : "r"(addr));
}

__device__ __forceinline__ void ldm_x4_trans(uint32_t& r0, uint32_t& r1, uint32_t& r2,
                                             uint32_t& r3, uint32_t addr) {
    asm volatile("ldmatrix.sync.aligned.m8n8.x4.trans.shared.b16 {%0,%1,%2,%3}, [%4];"
                 : "=r"(r0), "=r"(r1), "=r"(r2), "=r"(r3) : "r"(addr));
}

__device__ __forceinline__ void mma16816(float* c, const uint32_t* a,
                                         uint32_t b0, uint32_t b1) {
    asm volatile(
        "mma.sync.aligned.m16n8k16.row.col.f32.f16.f16.f32 "
        "{%0,%1,%2,%3}, {%4,%5,%6,%7}, {%8,%9}, {%0,%1,%2,%3};"
        : "+f"(c[0]), "+f"(c[1]), "+f"(c[2]), "+f"(c[3])
        : "r"(a[0]), "r"(a[1]), "r"(a[2]), "r"(a[3]), "r"(b0), "r"(b1));
}

// ---------------------------------------------------------------------------
// fp16 tensor-core GEMM with 2-stage smem pipeline.
// C[M,N] = half(A (+A2)) @ half(B) + bias (+Res); fp32 in/out.
// BM=128, BK=32, 256 threads (8 warps, 4x2), warp tile 32 x (BN/2).
// ---------------------------------------------------------------------------
template <int BN, bool HAS_A2, bool HAS_RES>
__global__ __launch_bounds__(256)
void hgemm_kernel(const float* __restrict__ A,
                  const float* __restrict__ A2,
                  const float* __restrict__ Bm,
                  const float* __restrict__ bias,
                  const float* __restrict__ Res,
                  float* __restrict__ Cout,
                  int M, int N, int K)
{
    constexpr int BM  = 128;
    constexpr int BK  = 32;
    constexpr int PAD = 8;
    constexpr int WTN = BN / 2;
    constexpr int NF  = WTN / 8;
    constexpr int NBR = BN / 32;     // B float4 loads per thread per tile

    __shared__ __half As[2][BM][BK + PAD];
    __shared__ __half Bs[2][BK][BN + PAD];

    const int tid  = threadIdx.x;
    const int warp = tid >> 5;
    const int lane = tid & 31;
    const int wm   = warp & 3;
    const int wn   = warp >> 2;
    const int m0   = blockIdx.y * BM;
    const int n0   = blockIdx.x * BN;

    float4 aR[4], a2R[4], bR[NBR];

    auto load_regs = [&](int k0) {
#pragma unroll
        for (int it = 0; it < 4; it++) {
            int idx = tid + it * 256;
            int r = idx >> 3, c4 = idx & 7;
            aR[it] = *(const float4*)(A + (size_t)(m0 + r) * K + k0 + c4 * 4);
            if (HAS_A2)
                a2R[it] = *(const float4*)(A2 + (size_t)(m0 + r) * K + k0 + c4 * 4);
        }
#pragma unroll
        for (int it = 0; it < NBR; it++) {
            int idx = tid + it * 256;
            int r = idx / (BN / 4), c = idx % (BN / 4);
            bR[it] = *(const float4*)(Bm + (size_t)(k0 + r) * N + n0 + c * 4);
        }
    };

    auto store_smem = [&](int buf) {
#pragma unroll
        for (int it = 0; it < 4; it++) {
            int idx = tid + it * 256;
            int r = idx >> 3, c4 = idx & 7;
            float x = aR[it].x, y = aR[it].y, z = aR[it].z, w = aR[it].w;
            if (HAS_A2) {
                x += a2R[it].x; y += a2R[it].y; z += a2R[it].z; w += a2R[it].w;
            }
            *(__half2*)&As[buf][r][c4 * 4]     = __floats2half2_rn(x, y);
            *(__half2*)&As[buf][r][c4 * 4 + 2] = __floats2half2_rn(z, w);
        }
#pragma unroll
        for (int it = 0; it < NBR; it++) {
            int idx = tid + it * 256;
            int r = idx / (BN / 4), c = idx % (BN / 4);
            *(__half2*)&Bs[buf][r][c * 4]     = __floats2half2_rn(bR[it].x, bR[it].y);
            *(__half2*)&Bs[buf][r][c * 4 + 2] = __floats2half2_rn(bR[it].z, bR[it].w);
        }
    };

    float acc[2][NF][4];
#pragma unroll
    for (int i = 0; i < 2; i++)
#pragma unroll
        for (int j = 0; j < NF; j++)
#pragma unroll
            for (int k = 0; k < 4; k++) acc[i][j][k] = 0.f;

    auto compute = [&](int buf) {
#pragma unroll
        for (int ks = 0; ks < 2; ks++) {
            uint32_t a[2][4];
#pragma unroll
            for (int mf = 0; mf < 2; mf++) {
                int row = wm * 32 + mf * 16 + (lane & 15);
                int col = ks * 16 + ((lane >> 4) << 3);
                ldm_x4(a[mf][0], a[mf][1], a[mf][2], a[mf][3],
                       smem_u32(&As[buf][row][col]));
            }
            uint32_t b[NF][2];
#pragma unroll
            for (int nb = 0; nb < NF / 2; nb++) {
                int g    = lane >> 3;
                int krow = ks * 16 + ((g & 1) << 3) + (lane & 7);
                int ncol = wn * WTN + nb * 16 + ((g >> 1) << 3);
                ldm_x4_trans(b[2 * nb][0], b[2 * nb][1],
                             b[2 * nb + 1][0], b[2 * nb + 1][1],
                             smem_u32(&Bs[buf][krow][ncol]));
            }
#pragma unroll
            for (int mf = 0; mf < 2; mf++)
#pragma unroll
                for (int nf = 0; nf < NF; nf++)
                    mma16816(acc[mf][nf], a[mf], b[nf][0], b[nf][1]);
        }
    };

    // ---- pipelined mainloop ----
    load_regs(0);
    store_smem(0);
    __syncthreads();
    int cur = 0;
    for (int k0 = 0; k0 < K; k0 += BK) {
        bool more = (k0 + BK) < K;
        if (more) load_regs(k0 + BK);
        compute(cur);
        if (more) {
            store_smem(cur ^ 1);
            __syncthreads();
        }
        cur ^= 1;
    }

    // ---- Epilogue ----
#pragma unroll
    for (int mf = 0; mf < 2; mf++) {
        int r = m0 + wm * 32 + mf * 16 + (lane >> 2);
#pragma unroll
        for (int nf = 0; nf < NF; nf++) {
            int c = n0 + wn * WTN + nf * 8 + ((lane & 3) << 1);
            float b0 = bias[c], b1 = bias[c + 1];
            size_t i0 = (size_t)r * N + c;
            size_t i1 = (size_t)(r + 8) * N + c;
            float2 o0 = make_float2(acc[mf][nf][0] + b0, acc[mf][nf][1] + b1);
            float2 o1 = make_float2(acc[mf][nf][2] + b0, acc[mf][nf][3] + b1);
            if (HAS_RES) {
                float2 q0 = *(const float2*)(Res + i0);
                float2 q1 = *(const float2*)(Res + i1);
                o0.x += q0.x; o0.y += q0.y;
                o1.x += q1.x; o1.y += q1.y;
            }
            *(float2*)(Cout + i0) = o0;
            *(float2*)(Cout + i1) = o1;
        }
    }
}

// ---------------------------------------------------------------------------
// Deformable sampling, float4 lanes: warp = (bq, 4 heads),
// lane = (head-in-group: lane>>3, channel-chunk: (lane&7)*4).
// Block = 256 threads = 8 warps = 4 bq. Grid = MTOT/4.
// ---------------------------------------------------------------------------
__global__ __launch_bounds__(256)
void deform_sample_kernel(const float* __restrict__ v,
                          const float* __restrict__ off,
                          const float* __restrict__ logits,
                          const float* __restrict__ ref,
                          float* __restrict__ mid)
{
    const int warp = threadIdx.x >> 5;
    const int lane = threadIdx.x & 31;
    const int bq   = blockIdx.x * 4 + (warp >> 1);
    const int h    = ((warp & 1) << 2) + (lane >> 3);   // 0..7
    const int d4   = (lane & 7) << 2;                   // 0,4,...,28
    const int b    = bq >> 14;

    const float rx = __ldg(&ref[bq * 2 + 0]) * (float)BEVW - 0.5f;
    const float ry = __ldg(&ref[bq * 2 + 1]) * (float)BEVH - 0.5f;

    const float4 lg = *(const float4*)(logits + bq * 32 + h * 4);
    float mx = fmaxf(fmaxf(lg.x, lg.y), fmaxf(lg.z, lg.w));
    float e0 = __expf(lg.x - mx), e1 = __expf(lg.y - mx);
    float e2 = __expf(lg.z - mx), e3 = __expf(lg.w - mx);
    float inv = 1.f / (e0 + e1 + e2 + e3);
    float aw[4] = {e0 * inv, e1 * inv, e2 * inv, e3 * inv};

    const float4 oA = *(const float4*)(off + (size_t)bq * 64 + h * 8);
    const float4 oB = *(const float4*)(off + (size_t)bq * 64 + h * 8 + 4);
    float ox[4] = {oA.x, oA.z, oB.x, oB.z};
    float oy[4] = {oA.y, oA.w, oB.y, oB.w};

    const float* vb = v + (size_t)b * QQ * CC + h * DD + d4;

    float4 acc = make_float4(0.f, 0.f, 0.f, 0.f);
#pragma unroll
    for (int p = 0; p < PP; p++) {
        float x = rx + ox[p];
        float y = ry + oy[p];
        float x0f = floorf(x), y0f = floorf(y);
        float dx = x - x0f, dy = y - y0f;
        int x0 = (int)x0f, y0 = (int)y0f;

        float wc[4];
        wc[0] = (1.f - dx) * (1.f - dy);
        wc[1] = dx * (1.f - dy);
        wc[2] = (1.f - dx) * dy;
        wc[3] = dx * dy;

        float4 sp = make_float4(0.f, 0.f, 0.f, 0.f);
#pragma unroll
        for (int c = 0; c < 4; c++) {
            int ix = x0 + (c & 1);
            int iy = y0 + (c >> 1);
            bool valid = (ix >= 0) & (ix < BEVW) & (iy >= 0) & (iy < BEVH);
            int cx = min(max(ix, 0), BEVW - 1);
            int cy = min(max(iy, 0), BEVH - 1);
            float w = valid ? wc[c] : 0.f;
            const float4 g = *(const float4*)(vb + (((cy << 7) + cx) << 8));
            sp.x = fmaf(g.x, w, sp.x);
            sp.y = fmaf(g.y, w, sp.y);
            sp.z = fmaf(g.z, w, sp.z);
            sp.w = fmaf(g.w, w, sp.w);
        }
        acc.x = fmaf(aw[p], sp.x, acc.x);
        acc.y = fmaf(aw[p], sp.y, acc.y);
        acc.z = fmaf(aw[p], sp.z, acc.z);
        acc.w = fmaf(aw[p], sp.w, acc.w);
    }

    *(float4*)(mid + (size_t)bq * CC + h * DD + d4) = acc;
}

// ---------------------------------------------------------------------------
// Launch
// ---------------------------------------------------------------------------
extern "C" void kernel_launch(void* const* d_in, const int* in_sizes, int n_in,
                              void* d_out, int out_size)
{
    const float* query     = (const float*)d_in[0];
    const float* value     = (const float*)d_in[1];
    const float* identity  = (const float*)d_in[2];
    const float* query_pos = (const float*)d_in[3];
    const float* refpts    = (const float*)d_in[4];
    const float* Wv   = (const float*)d_in[7];
    const float* bv   = (const float*)d_in[8];
    const float* Woff = (const float*)d_in[9];
    const float* boff = (const float*)d_in[10];
    const float* Ww   = (const float*)d_in[11];
    const float* bw   = (const float*)d_in[12];
    const float* Wo   = (const float*)d_in[13];
    const float* bo   = (const float*)d_in[14];
    float* out = (float*)d_out;

    float *pv, *pmid, *poff, *plog;
    cudaGetSymbolAddress((void**)&pv,   g_v);
    cudaGetSymbolAddress((void**)&pmid, g_mid);
    cudaGetSymbolAddress((void**)&poff, g_off);
    cudaGetSymbolAddress((void**)&plog, g_logits);

    // 1) v = value @ Wv + bv   (32768 x 256 x 256)
    hgemm_kernel<64, false, false>
        <<<dim3(CC / 64, MTOT / 128), 256>>>(value, nullptr, Wv, bv, nullptr, pv,
                                             MTOT, CC, CC);
    // 2) off = (q+qpos) @ Woff + boff   (32768 x 64 x 256)
    hgemm_kernel<64, true, false>
        <<<dim3(1, MTOT / 128), 256>>>(query, query_pos, Woff, boff, nullptr, poff,
                                       MTOT, 64, CC);
    // 3) logits = (q+qpos) @ Ww + bw   (32768 x 32 x 256)
    hgemm_kernel<32, true, false>
        <<<dim3(1, MTOT / 128), 256>>>(query, query_pos, Ww, bw, nullptr, plog,
                                       MTOT, 32, CC);
    // 4) softmax + bilinear sampling
    deform_sample_kernel<<<MTOT / 4, 256>>>(pv, poff, plog, refpts, pmid);
    // 5) out = mid @ Wo + bo + identity   (32768 x 256 x 256)
    hgemm_kernel<64, false, true>
        <<<dim3(CC / 64, MTOT / 128), 256>>>(pmid, nullptr, Wo, bo, identity, out,
                                             MTOT, CC, CC);
}

// round 4
// speedup vs baseline: 6.8278x; 1.2351x over previous
#include <cuda_runtime.h>
#include <cuda_fp16.h>
#include <cstdint>

// Problem constants
#define BB   2
#define QQ   16384
#define CC   256
#define HH   8
#define PP   4
#define DD   32
#define BEVW 128
#define BEVH 128
#define MTOT (BB*QQ)

// Scratch (fp16 intermediates)
__device__ __half g_v[MTOT * CC];
__device__ __half g_mid[MTOT * CC];
__device__ float  g_off[MTOT * 64];
__device__ float  g_logits[MTOT * 32];

// ---------------------------------------------------------------------------
// PTX helpers
// ---------------------------------------------------------------------------
__device__ __forceinline__ uint32_t smem_u32(const void* p) {
    uint32_t a;
    asm("{ .reg .u64 t; cvta.to.shared.u64 t, %1; cvt.u32.u64 %0, t; }"
        : "=r"(a) : "l"(p));
    return a;
}

__device__ __forceinline__ void ldm_x4(uint32_t& r0, uint32_t& r1, uint32_t& r2,
                                       uint32_t& r3, uint32_t addr) {
    asm volatile("ldmatrix.sync.aligned.m8n8.x4.shared.b16 {%0,%1,%2,%3}, [%4];"
                 : "=r"(r0), "=r"(r1), "=r"(r2), "=r"(r3) : "r"(addr));
}

__device__ __forceinline__ void ldm_x4_trans(uint32_t& r0, uint32_t& r1, uint32_t& r2,
                                             uint32_t& r3, uint32_t addr) {
    asm volatile("ldmatrix.sync.aligned.m8n8.x4.trans.shared.b16 {%0,%1,%2,%3}, [%4];"
                 : "=r"(r0), "=r"(r1), "=r"(r2), "=r"(r3) : "r"(addr));
}

__device__ __forceinline__ void mma16816(float* c, const uint32_t* a,
                                         uint32_t b0, uint32_t b1) {
    asm volatile(
        "mma.sync.aligned.m16n8k16.row.col.f32.f16.f16.f32 "
        "{%0,%1,%2,%3}, {%4,%5,%6,%7}, {%8,%9}, {%0,%1,%2,%3};"
        : "+f"(c[0]), "+f"(c[1]), "+f"(c[2]), "+f"(c[3])
        : "r"(a[0]), "r"(a[1]), "r"(a[2]), "r"(a[3]), "r"(b0), "r"(b1));
}

// ---------------------------------------------------------------------------
// BN=64 fp16 tensor-core GEMM, 2-stage pipeline.
// A: fp32 (optionally +A2) or fp16 direct (A_HALF). Output fp32 or fp16.
// BM=128, BK=32, 256 threads (8 warps, 4x2), warp tile 32x32.
// ---------------------------------------------------------------------------
template <bool HAS_A2, bool HAS_RES, bool OUT_HALF, bool A_HALF>
__global__ __launch_bounds__(256)
void hgemm64_kernel(const float* __restrict__ A,
                    const __half* __restrict__ Ah,
                    const float* __restrict__ A2,
                    const float* __restrict__ Bm,
                    const float* __restrict__ bias,
                    const float* __restrict__ Res,
                    void* __restrict__ Cout_,
                    int M, int N, int K)
{
    constexpr int BM  = 128;
    constexpr int BK  = 32;
    constexpr int PAD = 8;
    constexpr int NF  = 4;          // 32/8

    __shared__ __half As[2][BM][BK + PAD];
    __shared__ __half Bs[2][BK][64 + PAD];

    const int tid  = threadIdx.x;
    const int warp = tid >> 5;
    const int lane = tid & 31;
    const int wm   = warp & 3;
    const int wn   = warp >> 2;
    const int m0   = blockIdx.y * BM;
    const int n0   = blockIdx.x * 64;

    float4 aR[4], a2R[4], bR[2];
    uint4  ahR[2];

    auto load_regs = [&](int k0) {
        if (A_HALF) {
#pragma unroll
            for (int it = 0; it < 2; it++) {
                int idx = tid + it * 256;
                int r = idx >> 2, c = idx & 3;     // c: 8-half chunk
                ahR[it] = *(const uint4*)(Ah + (size_t)(m0 + r) * K + k0 + c * 8);
            }
        } else {
#pragma unroll
            for (int it = 0; it < 4; it++) {
                int idx = tid + it * 256;
                int r = idx >> 3, c4 = idx & 7;
                aR[it] = *(const float4*)(A + (size_t)(m0 + r) * K + k0 + c4 * 4);
                if (HAS_A2)
                    a2R[it] = *(const float4*)(A2 + (size_t)(m0 + r) * K + k0 + c4 * 4);
            }
        }
#pragma unroll
        for (int it = 0; it < 2; it++) {
            int idx = tid + it * 256;
            int r = idx >> 4, c = idx & 15;
            bR[it] = *(const float4*)(Bm + (size_t)(k0 + r) * N + n0 + c * 4);
        }
    };

    auto store_smem = [&](int buf) {
        if (A_HALF) {
#pragma unroll
            for (int it = 0; it < 2; it++) {
                int idx = tid + it * 256;
                int r = idx >> 2, c = idx & 3;
                *(uint4*)&As[buf][r][c * 8] = ahR[it];
            }
        } else {
#pragma unroll
            for (int it = 0; it < 4; it++) {
                int idx = tid + it * 256;
                int r = idx >> 3, c4 = idx & 7;
                float x = aR[it].x, y = aR[it].y, z = aR[it].z, w = aR[it].w;
                if (HAS_A2) {
                    x += a2R[it].x; y += a2R[it].y; z += a2R[it].z; w += a2R[it].w;
                }
                *(__half2*)&As[buf][r][c4 * 4]     = __floats2half2_rn(x, y);
                *(__half2*)&As[buf][r][c4 * 4 + 2] = __floats2half2_rn(z, w);
            }
        }
#pragma unroll
        for (int it = 0; it < 2; it++) {
            int idx = tid + it * 256;
            int r = idx >> 4, c = idx & 15;
            *(__half2*)&Bs[buf][r][c * 4]     = __floats2half2_rn(bR[it].x, bR[it].y);
            *(__half2*)&Bs[buf][r][c * 4 + 2] = __floats2half2_rn(bR[it].z, bR[it].w);
        }
    };

    float acc[2][NF][4];
#pragma unroll
    for (int i = 0; i < 2; i++)
#pragma unroll
        for (int j = 0; j < NF; j++)
#pragma unroll
            for (int k = 0; k < 4; k++) acc[i][j][k] = 0.f;

    auto compute = [&](int buf) {
#pragma unroll
        for (int ks = 0; ks < 2; ks++) {
            uint32_t a[2][4];
#pragma unroll
            for (int mf = 0; mf < 2; mf++) {
                int row = wm * 32 + mf * 16 + (lane & 15);
                int col = ks * 16 + ((lane >> 4) << 3);
                ldm_x4(a[mf][0], a[mf][1], a[mf][2], a[mf][3],
                       smem_u32(&As[buf][row][col]));
            }
            uint32_t b[NF][2];
#pragma unroll
            for (int nb = 0; nb < NF / 2; nb++) {
                int g    = lane >> 3;
                int krow = ks * 16 + ((g & 1) << 3) + (lane & 7);
                int ncol = wn * 32 + nb * 16 + ((g >> 1) << 3);
                ldm_x4_trans(b[2 * nb][0], b[2 * nb][1],
                             b[2 * nb + 1][0], b[2 * nb + 1][1],
                             smem_u32(&Bs[buf][krow][ncol]));
            }
#pragma unroll
            for (int mf = 0; mf < 2; mf++)
#pragma unroll
                for (int nf = 0; nf < NF; nf++)
                    mma16816(acc[mf][nf], a[mf], b[nf][0], b[nf][1]);
        }
    };

    load_regs(0);
    store_smem(0);
    __syncthreads();
    int cur = 0;
    for (int k0 = 0; k0 < K; k0 += BK) {
        bool more = (k0 + BK) < K;
        if (more) load_regs(k0 + BK);
        compute(cur);
        if (more) {
            store_smem(cur ^ 1);
            __syncthreads();
        }
        cur ^= 1;
    }

#pragma unroll
    for (int mf = 0; mf < 2; mf++) {
        int r = m0 + wm * 32 + mf * 16 + (lane >> 2);
#pragma unroll
        for (int nf = 0; nf < NF; nf++) {
            int c = n0 + wn * 32 + nf * 8 + ((lane & 3) << 1);
            float b0 = bias[c], b1 = bias[c + 1];
            size_t i0 = (size_t)r * N + c;
            size_t i1 = (size_t)(r + 8) * N + c;
            float2 o0 = make_float2(acc[mf][nf][0] + b0, acc[mf][nf][1] + b1);
            float2 o1 = make_float2(acc[mf][nf][2] + b0, acc[mf][nf][3] + b1);
            if (HAS_RES) {
                const float* Rp = Res;
                float2 q0 = *(const float2*)(Rp + i0);
                float2 q1 = *(const float2*)(Rp + i1);
                o0.x += q0.x; o0.y += q0.y;
                o1.x += q1.x; o1.y += q1.y;
            }
            if (OUT_HALF) {
                __half* Co = (__half*)Cout_;
                *(__half2*)(Co + i0) = __floats2half2_rn(o0.x, o0.y);
                *(__half2*)(Co + i1) = __floats2half2_rn(o1.x, o1.y);
            } else {
                float* Co = (float*)Cout_;
                *(float2*)(Co + i0) = o0;
                *(float2*)(Co + i1) = o1;
            }
        }
    }
}

// ---------------------------------------------------------------------------
// Fused offsets+logits GEMM: N=96 (cols 0-63 -> off via Woff/boff,
// cols 64-95 -> logits via Ww/bw). A = query + query_pos (fp32 -> fp16).
// BM=128, BK=32, 256 threads, warp tile 32x48 (NF=6).
// ---------------------------------------------------------------------------
__global__ __launch_bounds__(256)
void hgemm_dual_kernel(const float* __restrict__ A,
                       const float* __restrict__ A2,
                       const float* __restrict__ Woff,
                       const float* __restrict__ boff,
                       const float* __restrict__ Ww,
                       const float* __restrict__ bw,
                       float* __restrict__ Ooff,
                       float* __restrict__ Olog,
                       int M, int K)
{
    constexpr int BM  = 128;
    constexpr int BK  = 32;
    constexpr int PAD = 8;
    constexpr int BN  = 96;
    constexpr int NF  = 6;

    __shared__ __half As[2][BM][BK + PAD];
    __shared__ __half Bs[2][BK][BN + PAD];

    const int tid  = threadIdx.x;
    const int warp = tid >> 5;
    const int lane = tid & 31;
    const int wm   = warp & 3;
    const int wn   = warp >> 2;
    const int m0   = blockIdx.y * BM;

    float4 aR[4], a2R[4], bR[3];

    auto load_regs = [&](int k0) {
#pragma unroll
        for (int it = 0; it < 4; it++) {
            int idx = tid + it * 256;
            int r = idx >> 3, c4 = idx & 7;
            aR[it]  = *(const float4*)(A  + (size_t)(m0 + r) * K + k0 + c4 * 4);
            a2R[it] = *(const float4*)(A2 + (size_t)(m0 + r) * K + k0 + c4 * 4);
        }
#pragma unroll
        for (int it = 0; it < 3; it++) {
            int idx = tid + it * 256;
            int r = idx / 24, c4 = idx % 24;
            int col = c4 * 4;
            if (col < 64)
                bR[it] = *(const float4*)(Woff + (size_t)(k0 + r) * 64 + col);
            else
                bR[it] = *(const float4*)(Ww + (size_t)(k0 + r) * 32 + col - 64);
        }
    };

    auto store_smem = [&](int buf) {
#pragma unroll
        for (int it = 0; it < 4; it++) {
            int idx = tid + it * 256;
            int r = idx >> 3, c4 = idx & 7;
            float x = aR[it].x + a2R[it].x;
            float y = aR[it].y + a2R[it].y;
            float z = aR[it].z + a2R[it].z;
            float w = aR[it].w + a2R[it].w;
            *(__half2*)&As[buf][r][c4 * 4]     = __floats2half2_rn(x, y);
            *(__half2*)&As[buf][r][c4 * 4 + 2] = __floats2half2_rn(z, w);
        }
#pragma unroll
        for (int it = 0; it < 3; it++) {
            int idx = tid + it * 256;
            int r = idx / 24, c4 = idx % 24;
            *(__half2*)&Bs[buf][r][c4 * 4]     = __floats2half2_rn(bR[it].x, bR[it].y);
            *(__half2*)&Bs[buf][r][c4 * 4 + 2] = __floats2half2_rn(bR[it].z, bR[it].w);
        }
    };

    float acc[2][NF][4];
#pragma unroll
    for (int i = 0; i < 2; i++)
#pragma unroll
        for (int j = 0; j < NF; j++)
#pragma unroll
            for (int k = 0; k < 4; k++) acc[i][j][k] = 0.f;

    auto compute = [&](int buf) {
#pragma unroll
        for (int ks = 0; ks < 2; ks++) {
            uint32_t a[2][4];
#pragma unroll
            for (int mf = 0; mf < 2; mf++) {
                int row = wm * 32 + mf * 16 + (lane & 15);
                int col = ks * 16 + ((lane >> 4) << 3);
                ldm_x4(a[mf][0], a[mf][1], a[mf][2], a[mf][3],
                       smem_u32(&As[buf][row][col]));
            }
            uint32_t b[NF][2];
#pragma unroll
            for (int nb = 0; nb < NF / 2; nb++) {
                int g    = lane >> 3;
                int krow = ks * 16 + ((g & 1) << 3) + (lane & 7);
                int ncol = wn * 48 + nb * 16 + ((g >> 1) << 3);
                ldm_x4_trans(b[2 * nb][0], b[2 * nb][1],
                             b[2 * nb + 1][0], b[2 * nb + 1][1],
                             smem_u32(&Bs[buf][krow][ncol]));
            }
#pragma unroll
            for (int mf = 0; mf < 2; mf++)
#pragma unroll
                for (int nf = 0; nf < NF; nf++)
                    mma16816(acc[mf][nf], a[mf], b[nf][0], b[nf][1]);
        }
    };

    load_regs(0);
    store_smem(0);
    __syncthreads();
    int cur = 0;
    for (int k0 = 0; k0 < K; k0 += BK) {
        bool more = (k0 + BK) < K;
        if (more) load_regs(k0 + BK);
        compute(cur);
        if (more) {
            store_smem(cur ^ 1);
            __syncthreads();
        }
        cur ^= 1;
    }

#pragma unroll
    for (int mf = 0; mf < 2; mf++) {
        int r = m0 + wm * 32 + mf * 16 + (lane >> 2);
#pragma unroll
        for (int nf = 0; nf < NF; nf++) {
            int c = wn * 48 + nf * 8 + ((lane & 3) << 1);
            float bsv0, bsv1;
            float* O;
            int Nout, col;
            if (c < 64) { O = Ooff; Nout = 64; col = c;      bsv0 = boff[col]; bsv1 = boff[col + 1]; }
            else        { O = Olog; Nout = 32; col = c - 64; bsv0 = bw[col];   bsv1 = bw[col + 1]; }
            size_t i0 = (size_t)r * Nout + col;
            size_t i1 = (size_t)(r + 8) * Nout + col;
            *(float2*)(O + i0) = make_float2(acc[mf][nf][0] + bsv0, acc[mf][nf][1] + bsv1);
            *(float2*)(O + i1) = make_float2(acc[mf][nf][2] + bsv0, acc[mf][nf][3] + bsv1);
        }
    }
}

// ---------------------------------------------------------------------------
// Deformable sampling (fp16 v, fp16 mid).
// Warp = 1 bq x 8 heads; lane = (head: lane>>2, 8-half chunk: (lane&3)*8).
// Block = 256 threads = 8 warps = 8 bq. Grid = MTOT/8.
// ---------------------------------------------------------------------------
__global__ __launch_bounds__(256)
void deform_sample_kernel(const __half* __restrict__ v,
                          const float* __restrict__ off,
                          const float* __restrict__ logits,
                          const float* __restrict__ ref,
                          __half* __restrict__ mid)
{
    const int warp = threadIdx.x >> 5;
    const int lane = threadIdx.x & 31;
    const int bq   = blockIdx.x * 8 + warp;
    const int h    = lane >> 2;           // 0..7
    const int d8   = (lane & 3) << 3;     // 0,8,16,24
    const int b    = bq >> 14;

    const float rx = __ldg(&ref[bq * 2 + 0]) * (float)BEVW - 0.5f;
    const float ry = __ldg(&ref[bq * 2 + 1]) * (float)BEVH - 0.5f;

    const float4 lg = *(const float4*)(logits + bq * 32 + h * 4);
    float mx = fmaxf(fmaxf(lg.x, lg.y), fmaxf(lg.z, lg.w));
    float e0 = __expf(lg.x - mx), e1 = __expf(lg.y - mx);
    float e2 = __expf(lg.z - mx), e3 = __expf(lg.w - mx);
    float inv = 1.f / (e0 + e1 + e2 + e3);
    float aw[4] = {e0 * inv, e1 * inv, e2 * inv, e3 * inv};

    const float4 oA = *(const float4*)(off + (size_t)bq * 64 + h * 8);
    const float4 oB = *(const float4*)(off + (size_t)bq * 64 + h * 8 + 4);
    float ox[4] = {oA.x, oA.z, oB.x, oB.z};
    float oy[4] = {oA.y, oA.w, oB.y, oB.w};

    const __half* vb = v + (size_t)b * QQ * CC + h * DD + d8;

    float acc[8];
#pragma unroll
    for (int i = 0; i < 8; i++) acc[i] = 0.f;

#pragma unroll
    for (int p = 0; p < PP; p++) {
        float x = rx + ox[p];
        float y = ry + oy[p];
        float x0f = floorf(x), y0f = floorf(y);
        float dx = x - x0f, dy = y - y0f;
        int x0 = (int)x0f, y0 = (int)y0f;

        float wc[4];
        wc[0] = (1.f - dx) * (1.f - dy);
        wc[1] = dx * (1.f - dy);
        wc[2] = (1.f - dx) * dy;
        wc[3] = dx * dy;

        float sp[8];
#pragma unroll
        for (int i = 0; i < 8; i++) sp[i] = 0.f;

#pragma unroll
        for (int c = 0; c < 4; c++) {
            int ix = x0 + (c & 1);
            int iy = y0 + (c >> 1);
            bool valid = (ix >= 0) & (ix < BEVW) & (iy >= 0) & (iy < BEVH);
            int cx = min(max(ix, 0), BEVW - 1);
            int cy = min(max(iy, 0), BEVH - 1);
            float w = valid ? wc[c] : 0.f;
            const uint4 g = *(const uint4*)(vb + (((cy << 7) + cx) << 8));
            const __half2* gh = (const __half2*)&g;
#pragma unroll
            for (int i = 0; i < 4; i++) {
                float2 f = __half22float2(gh[i]);
                sp[2 * i]     = fmaf(f.x, w, sp[2 * i]);
                sp[2 * i + 1] = fmaf(f.y, w, sp[2 * i + 1]);
            }
        }
#pragma unroll
        for (int i = 0; i < 8; i++) acc[i] = fmaf(aw[p], sp[i], acc[i]);
    }

    uint4 o;
    __half2* oh = (__half2*)&o;
#pragma unroll
    for (int i = 0; i < 4; i++)
        oh[i] = __floats2half2_rn(acc[2 * i], acc[2 * i + 1]);
    *(uint4*)(mid + (size_t)bq * CC + h * DD + d8) = o;
}

// ---------------------------------------------------------------------------
// Launch
// ---------------------------------------------------------------------------
extern "C" void kernel_launch(void* const* d_in, const int* in_sizes, int n_in,
                              void* d_out, int out_size)
{
    const float* query     = (const float*)d_in[0];
    const float* value     = (const float*)d_in[1];
    const float* identity  = (const float*)d_in[2];
    const float* query_pos = (const float*)d_in[3];
    const float* refpts    = (const float*)d_in[4];
    const float* Wv   = (const float*)d_in[7];
    const float* bv   = (const float*)d_in[8];
    const float* Woff = (const float*)d_in[9];
    const float* boff = (const float*)d_in[10];
    const float* Ww   = (const float*)d_in[11];
    const float* bw   = (const float*)d_in[12];
    const float* Wo   = (const float*)d_in[13];
    const float* bo   = (const float*)d_in[14];
    float* out = (float*)d_out;

    __half *pv, *pmid;
    float *poff, *plog;
    cudaGetSymbolAddress((void**)&pv,   g_v);
    cudaGetSymbolAddress((void**)&pmid, g_mid);
    cudaGetSymbolAddress((void**)&poff, g_off);
    cudaGetSymbolAddress((void**)&plog, g_logits);

    // 1) v = value @ Wv + bv -> fp16   (32768 x 256 x 256)
    hgemm64_kernel<false, false, true, false>
        <<<dim3(CC / 64, MTOT / 128), 256>>>(value, nullptr, nullptr, Wv, bv,
                                             nullptr, pv, MTOT, CC, CC);
    // 2+3) off & logits fused   (32768 x 96 x 256)
    hgemm_dual_kernel<<<dim3(1, MTOT / 128), 256>>>(query, query_pos,
                                                    Woff, boff, Ww, bw,
                                                    poff, plog, MTOT, CC);
    // 4) softmax + bilinear sampling -> fp16 mid
    deform_sample_kernel<<<MTOT / 8, 256>>>(pv, poff, plog, refpts, pmid);
    // 5) out = mid @ Wo + bo + identity   (32768 x 256 x 256), A fp16 direct
    hgemm64_kernel<false, true, false, true>
        <<<dim3(CC / 64, MTOT / 128), 256>>>(nullptr, pmid, nullptr, Wo, bo,
                                             identity, out, MTOT, CC, CC);
}